// round 13
// baseline (speedup 1.0000x reference)
#include <cuda_runtime.h>
#include <cuda_bf16.h>
#include <cuda_fp16.h>
#include <cstdint>

#define NN  100000
#define EE  1600000
#define FIN 256
#define HD  128
#define CC  16
#define NB  ((NN + 511) / 512)   // scan blocks = 196

// Scratch (static device globals -- no allocation in kernel_launch)
__device__ int   g_cnt [NN];
__device__ float g_dinv[NN];
__device__ int   g_off [NN + 1];
__device__ int   g_cur [NN];
__device__ int   g_csr [EE];
__device__ int   g_bsum[NB];
__device__ __align__(16) __half g_hh[(size_t)NN * HD];   // h2 = dinv*(x@W), fp16
__device__ float g_w  [CC * HD];
__device__ float g_b  [CC];
__device__ int   g_i64;
// W in fp16, n-major: [n=128][k=256]
__device__ __align__(16) __half g_wf[HD * FIN];

// ---------------------------------------------------------------------------
// Helpers
// ---------------------------------------------------------------------------
__device__ __forceinline__ uint32_t smem_u32(const void* p) {
    uint32_t a;
    asm("{ .reg .u64 t; cvta.to.shared.u64 t, %1; cvt.u32.u64 %0, t; }" : "=r"(a) : "l"(p));
    return a;
}
#define SW128(o) ((o) ^ (((o) >> 3) & 0x70))

#define LDSM4(r0, r1, r2, r3, a) \
    asm volatile("ldmatrix.sync.aligned.m8n8.x4.shared.b16 {%0,%1,%2,%3}, [%4];" \
                 : "=r"(r0), "=r"(r1), "=r"(r2), "=r"(r3) : "r"(a))

#define MMA_F16(d, a0, a1, a2, a3, b0, b1) \
    asm volatile("mma.sync.aligned.m16n8k16.row.col.f32.f16.f16.f32 " \
                 "{%0,%1,%2,%3}, {%4,%5,%6,%7}, {%8,%9}, {%0,%1,%2,%3};" \
                 : "+f"((d)[0]), "+f"((d)[1]), "+f"((d)[2]), "+f"((d)[3]) \
                 : "r"(a0), "r"(a1), "r"(a2), "r"(a3), "r"(b0), "r"(b1))

// ---------------------------------------------------------------------------
// Init: zero degree counters; block 0 also detects edge_index dtype
// ---------------------------------------------------------------------------
__global__ void __launch_bounds__(256) k_init(const unsigned int* __restrict__ w, int n) {
    int i = blockIdx.x * blockDim.x + threadIdx.x;
    if (i < n) g_cnt[i] = 0;
    if (blockIdx.x == 0) {
        __shared__ unsigned int s[256];
        int tx = threadIdx.x;
        unsigned int acc = 0;
        #pragma unroll
        for (int j = tx; j < 1024; j += 256) acc |= w[2 * j + 1];
        s[tx] = acc;
        __syncthreads();
        for (int o = 128; o; o >>= 1) {
            if (tx < o) s[tx] |= s[tx + o];
            __syncthreads();
        }
        if (tx == 0) g_i64 = (s[0] == 0u) ? 1 : 0;
    }
}

__device__ __forceinline__ int load_idx(const void* ei, size_t i) {
    return g_i64 ? (int)((const long long*)ei)[i] : ((const int*)ei)[i];
}

__global__ void k_cnt(const void* __restrict__ ei, int e) {
    int i = blockIdx.x * blockDim.x + threadIdx.x;
    if (i < e) atomicAdd(&g_cnt[load_idx(ei, (size_t)e + i)], 1);
}

// ---------------------------------------------------------------------------
// Scan phase 1 (block sums) + dinv computation
// ---------------------------------------------------------------------------
__global__ void __launch_bounds__(512) k_scan1(int n) {
    __shared__ int s[512];
    int b = blockIdx.x, tx = threadIdx.x;
    int i = b * 512 + tx;
    int v = (i < n) ? g_cnt[i] : 0;
    if (i < n) g_dinv[i] = rsqrtf((float)(v + 1));   // +1 self loop
    s[tx] = v;
    __syncthreads();
    for (int o = 256; o; o >>= 1) {
        if (tx < o) s[tx] += s[tx + o];
        __syncthreads();
    }
    if (tx == 0) g_bsum[b] = s[0];
}

// Parallel scan of NB (<=256) block sums -> exclusive sums, single block
__global__ void __launch_bounds__(256) k_scan2(int n, int e) {
    __shared__ int s[256];
    int tx = threadIdx.x;
    int v = (tx < NB) ? g_bsum[tx] : 0;
    s[tx] = v;
    __syncthreads();
    #pragma unroll
    for (int o = 1; o < 256; o <<= 1) {
        int t = (tx >= o) ? s[tx - o] : 0;
        __syncthreads();
        s[tx] += t;
        __syncthreads();
    }
    if (tx < NB) g_bsum[tx] = s[tx] - v;   // exclusive
    if (tx == 0) g_off[n] = e;
}

__global__ void __launch_bounds__(512) k_scan3(int n) {
    __shared__ int s[512];
    int b = blockIdx.x, tx = threadIdx.x;
    int i = b * 512 + tx;
    int v = (i < n) ? g_cnt[i] : 0;
    s[tx] = v;
    __syncthreads();
    #pragma unroll
    for (int o = 1; o < 512; o <<= 1) {
        int t = (tx >= o) ? s[tx - o] : 0;
        __syncthreads();
        s[tx] += t;
        __syncthreads();
    }
    if (i < n) {
        int excl = s[tx] - v + g_bsum[b];
        g_off[i] = excl;
        g_cur[i] = excl;
    }
}

// ---------------------------------------------------------------------------
// CSR fill
// ---------------------------------------------------------------------------
__global__ void k_fill(const void* __restrict__ ei, int e) {
    int i = blockIdx.x * blockDim.x + threadIdx.x;
    if (i >= e) return;
    int s = load_idx(ei, (size_t)i);
    int d = load_idx(ei, (size_t)e + i);
    int p = atomicAdd(&g_cur[d], 1);
    g_csr[p] = s;
}

// ---------------------------------------------------------------------------
// Prep: blocks 0-127 convert W to fp16 (n-major); block 128 samples w/b
// ---------------------------------------------------------------------------
__global__ void __launch_bounds__(256) k_prep(const float* __restrict__ W,
                                              const float* __restrict__ wmu,
                                              const float* __restrict__ wls,
                                              const float* __restrict__ bmu,
                                              const float* __restrict__ bls,
                                              const float* __restrict__ ew,
                                              const float* __restrict__ eb) {
    int tx = threadIdx.x;
    if (blockIdx.x < 128) {
        int idx = blockIdx.x * 256 + tx;   // 0..32767
        int nn = idx >> 8;                 // 0..127
        int k  = idx & 255;                // 0..255
        g_wf[nn * FIN + k] = __float2half(W[(size_t)k * HD + nn]);
    } else {
        for (int i = tx; i < CC * HD; i += 256)
            g_w[i] = wmu[i] + expf(wls[i]) * ew[i];
        if (tx < CC)
            g_b[tx] = bmu[tx] + expf(bls[tx]) * eb[tx];
    }
}

// ---------------------------------------------------------------------------
// Tensor-core GEMM via mma.sync (single fp16 product, fp32 accum):
//   h2[row] = dinv[row] * (x[row] @ W)   -> stored fp16
// CTA tile M=64 x N=128, K = 4 chunks of 64; 8 warps (2x4), warp tile 32x32.
// Double-buffered 24KB stages (A 8KB + W 16KB), 48KB static smem.
// ---------------------------------------------------------------------------
#define STAGE   24576
#define OFF_W   8192

__global__ void __launch_bounds__(256) k_mmagemm(const float* __restrict__ x, int n) {
    __shared__ __align__(128) unsigned char sm[2 * STAGE];

    const int tx   = threadIdx.x;
    const int wid  = tx >> 5;
    const int lane = tx & 31;
    const int wr   = wid >> 2;       // 0..1
    const int wc   = wid & 3;        // 0..3
    const int row0 = blockIdx.x * 64;

    const uint32_t base = smem_u32(sm);

    uint32_t aoff[2], boff[2];
    #pragma unroll
    for (int ma = 0; ma < 2; ma++)
        aoff[ma] = (uint32_t)((wr * 32 + ma * 16 + (lane & 15)) * 128 + (lane >> 4) * 16);
    #pragma unroll
    for (int g = 0; g < 2; g++)
        boff[g] = (uint32_t)((wc * 32 + g * 16 + (lane & 15)) * 128 + (lane >> 4) * 16);

    float acc[2][4][4];
    #pragma unroll
    for (int i = 0; i < 2; i++)
        #pragma unroll
        for (int j = 0; j < 4; j++)
            #pragma unroll
            for (int q = 0; q < 4; q++) acc[i][j][q] = 0.f;

    float4 px[4];

    #define LOADX(c) do { \
        _Pragma("unroll") \
        for (int i = 0; i < 4; i++) { \
            int idx = tx + i * 256; \
            int row = idx >> 4, j = idx & 15; \
            int gr  = row0 + row; \
            px[i] = (gr < n) ? *(const float4*)(x + (size_t)gr * FIN + (c) * 64 + 4 * j) \
                             : make_float4(0.f, 0.f, 0.f, 0.f); \
        } } while (0)

    #define STORE(c, s) do { \
        unsigned char* sp = sm + (s) * STAGE; \
        _Pragma("unroll") \
        for (int i = 0; i < 4; i++) { \
            int idx = tx + i * 256; \
            int row = idx >> 4, j = idx & 15; \
            float4 f = px[i]; \
            __half2 p0 = __floats2half2_rn(f.x, f.y); \
            __half2 p1 = __floats2half2_rn(f.z, f.w); \
            uint32_t off = SW128((uint32_t)(row * 128 + 8 * j)); \
            *(uint2*)(sp + off) = make_uint2(*(uint32_t*)&p0, *(uint32_t*)&p1); \
        } \
        _Pragma("unroll") \
        for (int i = 0; i < 4; i++) { \
            int idx = tx + i * 256; \
            int nn = idx >> 3, u = idx & 7; \
            uint32_t off = SW128((uint32_t)(nn * 128 + 16 * u)); \
            *(uint4*)(sp + OFF_W + off) = *(const uint4*)(g_wf + nn * FIN + (c) * 64 + 8 * u); \
        } } while (0)

    LOADX(0);
    STORE(0, 0);
    LOADX(1);

    for (int c = 0; c < 4; c++) {
        __syncthreads();

        {
            uint32_t sb = base + (c & 1) * STAGE;
            #pragma unroll
            for (int ks = 0; ks < 4; ks++) {
                uint32_t ah[2][4];
                #pragma unroll
                for (int ma = 0; ma < 2; ma++) {
                    uint32_t o = SW128(aoff[ma] + ks * 32);
                    LDSM4(ah[ma][0], ah[ma][1], ah[ma][2], ah[ma][3], sb + o);
                }
                #pragma unroll
                for (int g = 0; g < 2; g++) {
                    uint32_t o = SW128(boff[g] + ks * 32);
                    uint32_t b0, b1, b2, b3;
                    LDSM4(b0, b1, b2, b3, sb + OFF_W + o);
                    #pragma unroll
                    for (int ma = 0; ma < 2; ma++) {
                        MMA_F16(acc[ma][2 * g],     ah[ma][0], ah[ma][1], ah[ma][2], ah[ma][3], b0, b2);
                        MMA_F16(acc[ma][2 * g + 1], ah[ma][0], ah[ma][1], ah[ma][2], ah[ma][3], b1, b3);
                    }
                }
            }
        }

        if (c < 3) STORE(c + 1, (c + 1) & 1);
        if (c < 2) LOADX(c + 2);
    }

    // --- Epilogue: scale by dinv[row], store fp16 h2 ---
    #pragma unroll
    for (int ma = 0; ma < 2; ma++) {
        int r1 = row0 + wr * 32 + ma * 16 + (lane >> 2);
        int r2 = r1 + 8;
        float d1 = (r1 < n) ? g_dinv[r1] : 0.f;
        float d2 = (r2 < n) ? g_dinv[r2] : 0.f;
        #pragma unroll
        for (int na = 0; na < 4; na++) {
            int col = wc * 32 + na * 8 + (lane & 3) * 2;
            if (r1 < n) {
                __half2 h = __floats2half2_rn(acc[ma][na][0] * d1, acc[ma][na][1] * d1);
                *(__half2*)&g_hh[(size_t)r1 * HD + col] = h;
            }
            if (r2 < n) {
                __half2 h = __floats2half2_rn(acc[ma][na][2] * d2, acc[ma][na][3] * d2);
                *(__half2*)&g_hh[(size_t)r2 * HD + col] = h;
            }
        }
    }
}

// ---------------------------------------------------------------------------
// Fused aggregation + classifier + log_softmax. One warp per node.
//   agg = sum over self+incoming of h2 (h2 is dinv-prescaled)
//   a = relu(agg*dinv[v] + gcn_b); logits = a @ w^T + b; out = log_softmax
// ---------------------------------------------------------------------------
__device__ __forceinline__ float4 h4_to_f4(uint2 u) {
    __half2 a = *reinterpret_cast<__half2*>(&u.x);
    __half2 b = *reinterpret_cast<__half2*>(&u.y);
    float2 fa = __half22float2(a);
    float2 fb = __half22float2(b);
    return make_float4(fa.x, fa.y, fb.x, fb.y);
}

__global__ void __launch_bounds__(256) k_aggf(const float* __restrict__ gcn_b,
                                              float* __restrict__ out, int n) {
    int w    = (blockIdx.x * blockDim.x + threadIdx.x) >> 5;
    int lane = threadIdx.x & 31;
    if (w >= n) return;

    const uint2* hp = reinterpret_cast<const uint2*>(g_hh);
    float4 acc = h4_to_f4(__ldg(hp + (size_t)w * 32 + lane));   // self loop

    int e0 = g_off[w], e1 = g_off[w + 1];
    for (int base = e0; base < e1; base += 32) {
        int m   = min(32, e1 - base);
        int idx = (base + lane < e1) ? g_csr[base + lane] : 0;
        int j = 0;
        for (; j + 4 <= m; j += 4) {
            int s0 = __shfl_sync(0xffffffffu, idx, j);
            int s1 = __shfl_sync(0xffffffffu, idx, j + 1);
            int s2 = __shfl_sync(0xffffffffu, idx, j + 2);
            int s3 = __shfl_sync(0xffffffffu, idx, j + 3);
            float4 v0 = h4_to_f4(__ldg(hp + (size_t)s0 * 32 + lane));
            float4 v1 = h4_to_f4(__ldg(hp + (size_t)s1 * 32 + lane));
            float4 v2 = h4_to_f4(__ldg(hp + (size_t)s2 * 32 + lane));
            float4 v3 = h4_to_f4(__ldg(hp + (size_t)s3 * 32 + lane));
            acc.x += v0.x; acc.y += v0.y; acc.z += v0.z; acc.w += v0.w;
            acc.x += v1.x; acc.y += v1.y; acc.z += v1.z; acc.w += v1.w;
            acc.x += v2.x; acc.y += v2.y; acc.z += v2.z; acc.w += v2.w;
            acc.x += v3.x; acc.y += v3.y; acc.z += v3.z; acc.w += v3.w;
        }
        for (; j < m; j++) {
            int s = __shfl_sync(0xffffffffu, idx, j);
            float4 v = h4_to_f4(__ldg(hp + (size_t)s * 32 + lane));
            acc.x += v.x; acc.y += v.y; acc.z += v.z; acc.w += v.w;
        }
    }

    // a = relu(acc*dinv + gcn_b)
    float dw = g_dinv[w];
    float4 gb = __ldg((const float4*)gcn_b + lane);
    float4 a;
    a.x = fmaxf(acc.x * dw + gb.x, 0.f);
    a.y = fmaxf(acc.y * dw + gb.y, 0.f);
    a.z = fmaxf(acc.z * dw + gb.z, 0.f);
    a.w = fmaxf(acc.w * dw + gb.w, 0.f);

    // logits: per-lane partials over the 4 owned columns, butterfly-reduce
    float p[16];
    #pragma unroll
    for (int c = 0; c < 16; c++) {
        float4 wv = __ldg((const float4*)(g_w + c * HD) + lane);
        p[c] = a.x * wv.x + a.y * wv.y + a.z * wv.z + a.w * wv.w;
    }
    #pragma unroll
    for (int off = 16; off; off >>= 1)
        #pragma unroll
        for (int c = 0; c < 16; c++)
            p[c] += __shfl_xor_sync(0xffffffffu, p[c], off);

    // bias + log_softmax (all lanes hold the full 16 logits)
    float m = -1e30f;
    #pragma unroll
    for (int c = 0; c < 16; c++) {
        p[c] += __ldg(&g_b[c]);
        m = fmaxf(m, p[c]);
    }
    float ss = 0.f;
    #pragma unroll
    for (int c = 0; c < 16; c++) ss += expf(p[c] - m);
    float ls = m + logf(ss);

    size_t ob = (size_t)w * CC;
    if (lane == 0)
        *(float4*)&out[ob]      = make_float4(p[0] - ls,  p[1] - ls,  p[2] - ls,  p[3] - ls);
    else if (lane == 1)
        *(float4*)&out[ob + 4]  = make_float4(p[4] - ls,  p[5] - ls,  p[6] - ls,  p[7] - ls);
    else if (lane == 2)
        *(float4*)&out[ob + 8]  = make_float4(p[8] - ls,  p[9] - ls,  p[10] - ls, p[11] - ls);
    else if (lane == 3)
        *(float4*)&out[ob + 12] = make_float4(p[12] - ls, p[13] - ls, p[14] - ls, p[15] - ls);
}

// ---------------------------------------------------------------------------
extern "C" void kernel_launch(void* const* d_in, const int* in_sizes, int n_in,
                              void* d_out, int out_size) {
    const float* x     = (const float*)d_in[0];
    const void*  ei    = d_in[1];
    const float* W     = (const float*)d_in[2];
    const float* gcn_b = (const float*)d_in[3];
    const float* w_mu  = (const float*)d_in[4];
    const float* w_ls  = (const float*)d_in[5];
    const float* b_mu  = (const float*)d_in[6];
    const float* b_ls  = (const float*)d_in[7];
    const float* eps_w = (const float*)d_in[8];
    const float* eps_b = (const float*)d_in[9];
    float* out = (float*)d_out;

    const int n = in_sizes[0] / FIN;
    const int e = in_sizes[1] / 2;

    static cudaStream_t s1 = nullptr;
    static cudaEvent_t  evF = nullptr, evD = nullptr, evG = nullptr;
    if (!s1) {
        cudaStreamCreateWithFlags(&s1, cudaStreamNonBlocking);
        cudaEventCreateWithFlags(&evF, cudaEventDisableTiming);
        cudaEventCreateWithFlags(&evD, cudaEventDisableTiming);
        cudaEventCreateWithFlags(&evG, cudaEventDisableTiming);
    }

    // fork: prep (W convert + bayes sample) has no dependencies -> s1 immediately
    cudaEventRecord(evF, 0);
    cudaStreamWaitEvent(s1, evF, 0);
    k_prep<<<129, 256, 0, s1>>>(W, w_mu, w_ls, b_mu, b_ls, eps_w, eps_b);

    // main: init -> cnt -> scan1 produces dinv
    k_init <<<(n + 255) / 256, 256>>>((const unsigned int*)ei, n);
    k_cnt  <<<(e + 255) / 256, 256>>>(ei, e);
    k_scan1<<<NB, 512>>>(n);
    cudaEventRecord(evD, 0);

    // s1: gemm needs dinv (epilogue prescale); overlaps scan2/scan3/fill
    cudaStreamWaitEvent(s1, evD, 0);
    k_mmagemm<<<(n + 63) / 64, 256, 0, s1>>>(x, n);
    cudaEventRecord(evG, s1);

    // main: rest of CSR build
    k_scan2<<<1, 256>>>(n, e);
    k_scan3<<<NB, 512>>>(n);
    k_fill <<<(e + 255) / 256, 256>>>(ei, e);

    // join: fused aggregation + classifier needs CSR + h2
    cudaStreamWaitEvent(0, evG, 0);
    k_aggf <<<(n * 32 + 255) / 256, 256>>>(gcn_b, out, n);
}

// round 14
// speedup vs baseline: 1.0498x; 1.0498x over previous
#include <cuda_runtime.h>
#include <cuda_bf16.h>
#include <cuda_fp16.h>
#include <cstdint>

#define NN  100000
#define EE  1600000
#define FIN 256
#define HD  128
#define CC  16
#define NB  ((NN + 511) / 512)   // scan blocks = 196

// Scratch (static device globals -- no allocation in kernel_launch)
__device__ int   g_cnt [NN];
__device__ float g_dinv[NN];
__device__ int   g_off [NN + 1];
__device__ int   g_cur [NN];
__device__ int   g_csr [EE];
__device__ int   g_bsum[NB];
__device__ __align__(16) __half g_hh  [(size_t)NN * HD];   // h2 = dinv*(x@W), fp16
__device__ __align__(16) __half g_acch[(size_t)NN * HD];   // aggregated sums, fp16
__device__ float g_w  [CC * HD];
__device__ float g_b  [CC];
__device__ int   g_i64;
// W in fp16, n-major: [n=128][k=256]
__device__ __align__(16) __half g_wf[HD * FIN];

// ---------------------------------------------------------------------------
// Helpers
// ---------------------------------------------------------------------------
__device__ __forceinline__ uint32_t smem_u32(const void* p) {
    uint32_t a;
    asm("{ .reg .u64 t; cvta.to.shared.u64 t, %1; cvt.u32.u64 %0, t; }" : "=r"(a) : "l"(p));
    return a;
}
#define SW128(o) ((o) ^ (((o) >> 3) & 0x70))

#define LDSM4(r0, r1, r2, r3, a) \
    asm volatile("ldmatrix.sync.aligned.m8n8.x4.shared.b16 {%0,%1,%2,%3}, [%4];" \
                 : "=r"(r0), "=r"(r1), "=r"(r2), "=r"(r3) : "r"(a))

#define MMA_F16(d, a0, a1, a2, a3, b0, b1) \
    asm volatile("mma.sync.aligned.m16n8k16.row.col.f32.f16.f16.f32 " \
                 "{%0,%1,%2,%3}, {%4,%5,%6,%7}, {%8,%9}, {%0,%1,%2,%3};" \
                 : "+f"((d)[0]), "+f"((d)[1]), "+f"((d)[2]), "+f"((d)[3]) \
                 : "r"(a0), "r"(a1), "r"(a2), "r"(a3), "r"(b0), "r"(b1))

// ---------------------------------------------------------------------------
// Init: zero degree counters; block 0 also detects edge_index dtype
// ---------------------------------------------------------------------------
__global__ void __launch_bounds__(256) k_init(const unsigned int* __restrict__ w, int n) {
    int i = blockIdx.x * blockDim.x + threadIdx.x;
    if (i < n) g_cnt[i] = 0;
    if (blockIdx.x == 0) {
        __shared__ unsigned int s[256];
        int tx = threadIdx.x;
        unsigned int acc = 0;
        #pragma unroll
        for (int j = tx; j < 1024; j += 256) acc |= w[2 * j + 1];
        s[tx] = acc;
        __syncthreads();
        for (int o = 128; o; o >>= 1) {
            if (tx < o) s[tx] |= s[tx + o];
            __syncthreads();
        }
        if (tx == 0) g_i64 = (s[0] == 0u) ? 1 : 0;
    }
}

__device__ __forceinline__ int load_idx(const void* ei, size_t i) {
    return g_i64 ? (int)((const long long*)ei)[i] : ((const int*)ei)[i];
}

__global__ void k_cnt(const void* __restrict__ ei, int e) {
    int i = blockIdx.x * blockDim.x + threadIdx.x;
    if (i < e) atomicAdd(&g_cnt[load_idx(ei, (size_t)e + i)], 1);
}

// ---------------------------------------------------------------------------
// Scan phase 1 (block sums) + dinv computation
// ---------------------------------------------------------------------------
__global__ void __launch_bounds__(512) k_scan1(int n) {
    __shared__ int s[512];
    int b = blockIdx.x, tx = threadIdx.x;
    int i = b * 512 + tx;
    int v = (i < n) ? g_cnt[i] : 0;
    if (i < n) g_dinv[i] = rsqrtf((float)(v + 1));   // +1 self loop
    s[tx] = v;
    __syncthreads();
    for (int o = 256; o; o >>= 1) {
        if (tx < o) s[tx] += s[tx + o];
        __syncthreads();
    }
    if (tx == 0) g_bsum[b] = s[0];
}

// Parallel scan of NB (<=256) block sums -> exclusive sums, single block
__global__ void __launch_bounds__(256) k_scan2(int n, int e) {
    __shared__ int s[256];
    int tx = threadIdx.x;
    int v = (tx < NB) ? g_bsum[tx] : 0;
    s[tx] = v;
    __syncthreads();
    #pragma unroll
    for (int o = 1; o < 256; o <<= 1) {
        int t = (tx >= o) ? s[tx - o] : 0;
        __syncthreads();
        s[tx] += t;
        __syncthreads();
    }
    if (tx < NB) g_bsum[tx] = s[tx] - v;   // exclusive
    if (tx == 0) g_off[n] = e;
}

__global__ void __launch_bounds__(512) k_scan3(int n) {
    __shared__ int s[512];
    int b = blockIdx.x, tx = threadIdx.x;
    int i = b * 512 + tx;
    int v = (i < n) ? g_cnt[i] : 0;
    s[tx] = v;
    __syncthreads();
    #pragma unroll
    for (int o = 1; o < 512; o <<= 1) {
        int t = (tx >= o) ? s[tx - o] : 0;
        __syncthreads();
        s[tx] += t;
        __syncthreads();
    }
    if (i < n) {
        int excl = s[tx] - v + g_bsum[b];
        g_off[i] = excl;
        g_cur[i] = excl;
    }
}

// ---------------------------------------------------------------------------
// CSR fill
// ---------------------------------------------------------------------------
__global__ void k_fill(const void* __restrict__ ei, int e) {
    int i = blockIdx.x * blockDim.x + threadIdx.x;
    if (i >= e) return;
    int s = load_idx(ei, (size_t)i);
    int d = load_idx(ei, (size_t)e + i);
    int p = atomicAdd(&g_cur[d], 1);
    g_csr[p] = s;
}

// ---------------------------------------------------------------------------
// Prep: blocks 0-127 convert W to fp16 (n-major); block 128 samples w/b
// ---------------------------------------------------------------------------
__global__ void __launch_bounds__(256) k_prep(const float* __restrict__ W,
                                              const float* __restrict__ wmu,
                                              const float* __restrict__ wls,
                                              const float* __restrict__ bmu,
                                              const float* __restrict__ bls,
                                              const float* __restrict__ ew,
                                              const float* __restrict__ eb) {
    int tx = threadIdx.x;
    if (blockIdx.x < 128) {
        int idx = blockIdx.x * 256 + tx;   // 0..32767
        int nn = idx >> 8;                 // 0..127
        int k  = idx & 255;                // 0..255
        g_wf[nn * FIN + k] = __float2half(W[(size_t)k * HD + nn]);
    } else {
        for (int i = tx; i < CC * HD; i += 256)
            g_w[i] = wmu[i] + expf(wls[i]) * ew[i];
        if (tx < CC)
            g_b[tx] = bmu[tx] + expf(bls[tx]) * eb[tx];
    }
}

// ---------------------------------------------------------------------------
// Tensor-core GEMM via mma.sync (single fp16 product, fp32 accum):
//   h2[row] = dinv[row] * (x[row] @ W)   -> stored fp16
// CTA tile M=64 x N=128, K = 4 chunks of 64; 8 warps (2x4), warp tile 32x32.
// Double-buffered 24KB stages (A 8KB + W 16KB), 48KB static smem.
// ---------------------------------------------------------------------------
#define STAGE   24576
#define OFF_W   8192

__global__ void __launch_bounds__(256) k_mmagemm(const float* __restrict__ x, int n) {
    __shared__ __align__(128) unsigned char sm[2 * STAGE];

    const int tx   = threadIdx.x;
    const int wid  = tx >> 5;
    const int lane = tx & 31;
    const int wr   = wid >> 2;       // 0..1
    const int wc   = wid & 3;        // 0..3
    const int row0 = blockIdx.x * 64;

    const uint32_t base = smem_u32(sm);

    uint32_t aoff[2], boff[2];
    #pragma unroll
    for (int ma = 0; ma < 2; ma++)
        aoff[ma] = (uint32_t)((wr * 32 + ma * 16 + (lane & 15)) * 128 + (lane >> 4) * 16);
    #pragma unroll
    for (int g = 0; g < 2; g++)
        boff[g] = (uint32_t)((wc * 32 + g * 16 + (lane & 15)) * 128 + (lane >> 4) * 16);

    float acc[2][4][4];
    #pragma unroll
    for (int i = 0; i < 2; i++)
        #pragma unroll
        for (int j = 0; j < 4; j++)
            #pragma unroll
            for (int q = 0; q < 4; q++) acc[i][j][q] = 0.f;

    float4 px[4];

    #define LOADX(c) do { \
        _Pragma("unroll") \
        for (int i = 0; i < 4; i++) { \
            int idx = tx + i * 256; \
            int row = idx >> 4, j = idx & 15; \
            int gr  = row0 + row; \
            px[i] = (gr < n) ? *(const float4*)(x + (size_t)gr * FIN + (c) * 64 + 4 * j) \
                             : make_float4(0.f, 0.f, 0.f, 0.f); \
        } } while (0)

    #define STORE(c, s) do { \
        unsigned char* sp = sm + (s) * STAGE; \
        _Pragma("unroll") \
        for (int i = 0; i < 4; i++) { \
            int idx = tx + i * 256; \
            int row = idx >> 4, j = idx & 15; \
            float4 f = px[i]; \
            __half2 p0 = __floats2half2_rn(f.x, f.y); \
            __half2 p1 = __floats2half2_rn(f.z, f.w); \
            uint32_t off = SW128((uint32_t)(row * 128 + 8 * j)); \
            *(uint2*)(sp + off) = make_uint2(*(uint32_t*)&p0, *(uint32_t*)&p1); \
        } \
        _Pragma("unroll") \
        for (int i = 0; i < 4; i++) { \
            int idx = tx + i * 256; \
            int nn = idx >> 3, u = idx & 7; \
            uint32_t off = SW128((uint32_t)(nn * 128 + 16 * u)); \
            *(uint4*)(sp + OFF_W + off) = *(const uint4*)(g_wf + nn * FIN + (c) * 64 + 8 * u); \
        } } while (0)

    LOADX(0);
    STORE(0, 0);
    LOADX(1);

    for (int c = 0; c < 4; c++) {
        __syncthreads();

        {
            uint32_t sb = base + (c & 1) * STAGE;
            #pragma unroll
            for (int ks = 0; ks < 4; ks++) {
                uint32_t ah[2][4];
                #pragma unroll
                for (int ma = 0; ma < 2; ma++) {
                    uint32_t o = SW128(aoff[ma] + ks * 32);
                    LDSM4(ah[ma][0], ah[ma][1], ah[ma][2], ah[ma][3], sb + o);
                }
                #pragma unroll
                for (int g = 0; g < 2; g++) {
                    uint32_t o = SW128(boff[g] + ks * 32);
                    uint32_t b0, b1, b2, b3;
                    LDSM4(b0, b1, b2, b3, sb + OFF_W + o);
                    #pragma unroll
                    for (int ma = 0; ma < 2; ma++) {
                        MMA_F16(acc[ma][2 * g],     ah[ma][0], ah[ma][1], ah[ma][2], ah[ma][3], b0, b2);
                        MMA_F16(acc[ma][2 * g + 1], ah[ma][0], ah[ma][1], ah[ma][2], ah[ma][3], b1, b3);
                    }
                }
            }
        }

        if (c < 3) STORE(c + 1, (c + 1) & 1);
        if (c < 2) LOADX(c + 2);
    }

    // --- Epilogue: scale by dinv[row], store fp16 h2 ---
    #pragma unroll
    for (int ma = 0; ma < 2; ma++) {
        int r1 = row0 + wr * 32 + ma * 16 + (lane >> 2);
        int r2 = r1 + 8;
        float d1 = (r1 < n) ? g_dinv[r1] : 0.f;
        float d2 = (r2 < n) ? g_dinv[r2] : 0.f;
        #pragma unroll
        for (int na = 0; na < 4; na++) {
            int col = wc * 32 + na * 8 + (lane & 3) * 2;
            if (r1 < n) {
                __half2 h = __floats2half2_rn(acc[ma][na][0] * d1, acc[ma][na][1] * d1);
                *(__half2*)&g_hh[(size_t)r1 * HD + col] = h;
            }
            if (r2 < n) {
                __half2 h = __floats2half2_rn(acc[ma][na][2] * d2, acc[ma][na][3] * d2);
                *(__half2*)&g_hh[(size_t)r2 * HD + col] = h;
            }
        }
    }
}

// ---------------------------------------------------------------------------
// Aggregation (pure gather sum): acc[v] = h2[v] + sum_{e: dst=v} h2[csr[e]]
// One warp per node; lane owns 4 cols (one uint2 of fp16). Result stored fp16.
// ---------------------------------------------------------------------------
__device__ __forceinline__ float4 h4_to_f4(uint2 u) {
    __half2 a = *reinterpret_cast<__half2*>(&u.x);
    __half2 b = *reinterpret_cast<__half2*>(&u.y);
    float2 fa = __half22float2(a);
    float2 fb = __half22float2(b);
    return make_float4(fa.x, fa.y, fb.x, fb.y);
}

__global__ void __launch_bounds__(256) k_agg(int n) {
    int w    = (blockIdx.x * blockDim.x + threadIdx.x) >> 5;
    int lane = threadIdx.x & 31;
    if (w >= n) return;

    const uint2* hp = reinterpret_cast<const uint2*>(g_hh);
    float4 acc = h4_to_f4(__ldg(hp + (size_t)w * 32 + lane));   // self loop

    int e0 = g_off[w], e1 = g_off[w + 1];
    for (int base = e0; base < e1; base += 32) {
        int m   = min(32, e1 - base);
        int idx = (base + lane < e1) ? g_csr[base + lane] : 0;
        int j = 0;
        for (; j + 4 <= m; j += 4) {
            int s0 = __shfl_sync(0xffffffffu, idx, j);
            int s1 = __shfl_sync(0xffffffffu, idx, j + 1);
            int s2 = __shfl_sync(0xffffffffu, idx, j + 2);
            int s3 = __shfl_sync(0xffffffffu, idx, j + 3);
            float4 v0 = h4_to_f4(__ldg(hp + (size_t)s0 * 32 + lane));
            float4 v1 = h4_to_f4(__ldg(hp + (size_t)s1 * 32 + lane));
            float4 v2 = h4_to_f4(__ldg(hp + (size_t)s2 * 32 + lane));
            float4 v3 = h4_to_f4(__ldg(hp + (size_t)s3 * 32 + lane));
            acc.x += v0.x; acc.y += v0.y; acc.z += v0.z; acc.w += v0.w;
            acc.x += v1.x; acc.y += v1.y; acc.z += v1.z; acc.w += v1.w;
            acc.x += v2.x; acc.y += v2.y; acc.z += v2.z; acc.w += v2.w;
            acc.x += v3.x; acc.y += v3.y; acc.z += v3.z; acc.w += v3.w;
        }
        for (; j < m; j++) {
            int s = __shfl_sync(0xffffffffu, idx, j);
            float4 v = h4_to_f4(__ldg(hp + (size_t)s * 32 + lane));
            acc.x += v.x; acc.y += v.y; acc.z += v.z; acc.w += v.w;
        }
    }

    __half2 o0 = __floats2half2_rn(acc.x, acc.y);
    __half2 o1 = __floats2half2_rn(acc.z, acc.w);
    reinterpret_cast<uint2*>(g_acch)[(size_t)w * 32 + lane] =
        make_uint2(*(uint32_t*)&o0, *(uint32_t*)&o1);
}

// ---------------------------------------------------------------------------
// Finalize: a = relu(dinv*acc + gcn_b); logits = a @ w^T + b; log_softmax.
// ---------------------------------------------------------------------------
__global__ void __launch_bounds__(256) k_final(const float* __restrict__ gcn_b,
                                               float* __restrict__ out, int n) {
    __shared__ float a_s[16][132];
    __shared__ float w_s[16][132];
    __shared__ float gb[128];
    __shared__ float b_s[16];

    const int tx = threadIdx.x;

    #pragma unroll
    for (int i = 0; i < 8; i++) {
        int idx = tx + i * 256;
        w_s[idx >> 7][idx & 127] = g_w[idx];
    }
    if (tx < 128) gb[tx] = gcn_b[tx];
    if (tx < 16)  b_s[tx] = g_b[tx];

    const int n0 = blockIdx.x * 16;
    __syncthreads();

    #pragma unroll
    for (int i = 0; i < 8; i++) {
        int idx  = tx + i * 256;
        int node = idx >> 7, h = idx & 127;
        int g    = n0 + node;
        float v  = 0.f;
        if (g < n)
            v = fmaxf(__half2float(g_acch[(size_t)g * HD + h]) * g_dinv[g] + gb[h], 0.f);
        a_s[node][h] = v;
    }
    __syncthreads();

    const int c    = tx & 15;
    const int node = tx >> 4;

    float lg = b_s[c];
    const float4* ap = (const float4*)&a_s[node][0];
    const float4* wp = (const float4*)&w_s[c][0];
    #pragma unroll
    for (int k = 0; k < 32; k++) {
        float4 av = ap[k];
        float4 wv = wp[k];
        lg += av.x * wv.x + av.y * wv.y + av.z * wv.z + av.w * wv.w;
    }

    float m = lg;
    #pragma unroll
    for (int o = 8; o; o >>= 1) m = fmaxf(m, __shfl_xor_sync(0xffffffffu, m, o));
    float ex = expf(lg - m);
    float ss = ex;
    #pragma unroll
    for (int o = 8; o; o >>= 1) ss += __shfl_xor_sync(0xffffffffu, ss, o);

    if (n0 + node < n)
        out[(size_t)(n0 + node) * CC + c] = lg - m - logf(ss);
}

// ---------------------------------------------------------------------------
extern "C" void kernel_launch(void* const* d_in, const int* in_sizes, int n_in,
                              void* d_out, int out_size) {
    const float* x     = (const float*)d_in[0];
    const void*  ei    = d_in[1];
    const float* W     = (const float*)d_in[2];
    const float* gcn_b = (const float*)d_in[3];
    const float* w_mu  = (const float*)d_in[4];
    const float* w_ls  = (const float*)d_in[5];
    const float* b_mu  = (const float*)d_in[6];
    const float* b_ls  = (const float*)d_in[7];
    const float* eps_w = (const float*)d_in[8];
    const float* eps_b = (const float*)d_in[9];
    float* out = (float*)d_out;

    const int n = in_sizes[0] / FIN;
    const int e = in_sizes[1] / 2;

    static cudaStream_t s1 = nullptr;
    static cudaEvent_t  evF = nullptr, evD = nullptr, evG = nullptr;
    if (!s1) {
        cudaStreamCreateWithFlags(&s1, cudaStreamNonBlocking);
        cudaEventCreateWithFlags(&evF, cudaEventDisableTiming);
        cudaEventCreateWithFlags(&evD, cudaEventDisableTiming);
        cudaEventCreateWithFlags(&evG, cudaEventDisableTiming);
    }

    // fork: prep (W convert + bayes sample) has no dependencies -> s1 immediately
    cudaEventRecord(evF, 0);
    cudaStreamWaitEvent(s1, evF, 0);
    k_prep<<<129, 256, 0, s1>>>(W, w_mu, w_ls, b_mu, b_ls, eps_w, eps_b);

    // main: init -> cnt -> scan1 produces dinv
    k_init <<<(n + 255) / 256, 256>>>((const unsigned int*)ei, n);
    k_cnt  <<<(e + 255) / 256, 256>>>(ei, e);
    k_scan1<<<NB, 512>>>(n);
    cudaEventRecord(evD, 0);

    // s1: gemm needs dinv (epilogue prescale); overlaps scan2/scan3/fill
    cudaStreamWaitEvent(s1, evD, 0);
    k_mmagemm<<<(n + 63) / 64, 256, 0, s1>>>(x, n);
    cudaEventRecord(evG, s1);

    // main: rest of CSR build
    k_scan2<<<1, 256>>>(n, e);
    k_scan3<<<NB, 512>>>(n);
    k_fill <<<(e + 255) / 256, 256>>>(ei, e);

    // join: aggregation needs CSR + h2
    cudaStreamWaitEvent(0, evG, 0);
    k_agg  <<<(n * 32 + 255) / 256, 256>>>(n);
    k_final<<<(n + 15) / 16, 256>>>(gcn_b, out, n);
}